// round 7
// baseline (speedup 1.0000x reference)
#include <cuda_runtime.h>
#include <cstdint>

#define DM   1024
#define NH   16
#define DKH  64
#define BB   4
#define TS   2048
#define MTOT (BB*TS)        // 8192
#define ELEMS (MTOT*DM)     // 8388608

// Scratch (static device memory — no allocation allowed)
__device__ float g_q[ELEMS];
__device__ float g_k[ELEMS];
__device__ float g_v[ELEMS];
__device__ float g_y[ELEMS];

// RNA tf32 rounding — value-preserving float form (for smem fills / P store)
__device__ __forceinline__ float tfr(float f) {
    unsigned u;
    asm("cvt.rna.tf32.f32 %0, %1;" : "=r"(u) : "f"(f));
    return __uint_as_float(u);
}
// RNA tf32 rounding — bit form for MMA fragments
__device__ __forceinline__ unsigned ldtf(float f) {
    unsigned u;
    asm("cvt.rna.tf32.f32 %0, %1;" : "=r"(u) : "f"(f));
    return u;
}

__device__ __forceinline__ void mma8(float* d, const unsigned* a, const unsigned* b) {
    asm volatile(
        "mma.sync.aligned.m16n8k8.row.col.f32.tf32.tf32.f32 "
        "{%0,%1,%2,%3}, {%4,%5,%6,%7}, {%8,%9}, {%0,%1,%2,%3};\n"
        : "+f"(d[0]), "+f"(d[1]), "+f"(d[2]), "+f"(d[3])
        : "r"(a[0]), "r"(a[1]), "r"(a[2]), "r"(a[3]), "r"(b[0]), "r"(b[1]));
}

__device__ __forceinline__ void cpa16(void* smem, const void* g) {
    unsigned s = (unsigned)__cvta_generic_to_shared(smem);
    asm volatile("cp.async.cg.shared.global [%0], [%1], 16;" :: "r"(s), "l"(g));
}
__device__ __forceinline__ void cpa_commit() {
    asm volatile("cp.async.commit_group;");
}
template <int N>
__device__ __forceinline__ void cpa_wait() {
    asm volatile("cp.async.wait_group %0;" :: "n"(N));
}

// ---------------------------------------------------------------------------
// C[M,N] = A[M,K] @ B[N,K]^T + bias.  MODE 0: plain row-major write.
// MODE 1: scatter into q/k/v [B,H,T,64] layouts, Q scaled by 1/sqrt(dk).
// BM=128, BN=256, BK=16; 256 threads = 8 warps, warp tile 64x64.
// cp.async double-buffered; RNA tf32 rounding applied on fragment load.
// ---------------------------------------------------------------------------
#define GA_STR 20
#define GA_BUF (128 * GA_STR)   // 2560 floats per A buffer
#define GB_BUF (256 * GA_STR)   // 5120 floats per B buffer

template <int MODE>
__global__ void __launch_bounds__(256, 1) gemm_tn(
    const float* __restrict__ A, const float* __restrict__ Bm,
    const float* __restrict__ bias, float* __restrict__ C,
    float* __restrict__ qb, float* __restrict__ kb, float* __restrict__ vb,
    int M, int N, int K)
{
    extern __shared__ float sm[];
    float* As = sm;                 // [2][128][20]
    float* Bs = sm + 2 * GA_BUF;    // [2][256][20]

    const int tid  = threadIdx.x;
    const int lane = tid & 31;
    const int warp = tid >> 5;
    const int wm = warp >> 2;     // 0..1
    const int wn = warp & 3;      // 0..3
    const int bm = blockIdx.y * 128;
    const int bn = blockIdx.x * 256;

    float acc[4][8][4];
#pragma unroll
    for (int mi = 0; mi < 4; mi++)
#pragma unroll
        for (int ni = 0; ni < 8; ni++)
#pragma unroll
            for (int q = 0; q < 4; q++) acc[mi][ni][q] = 0.0f;

    const int NT = K >> 4;

    // tile loader: As 512 float4s (2/thread), Bs 1024 float4s (4/thread)
    auto load_tile = [&](int kt, int buf) {
#pragma unroll
        for (int i = 0; i < 2; i++) {
            int idx = i * 256 + tid;
            int r = idx >> 2, c = (idx & 3) * 4;
            cpa16(&As[buf * GA_BUF + r * GA_STR + c],
                  A + (size_t)(bm + r) * K + kt + c);
        }
#pragma unroll
        for (int i = 0; i < 4; i++) {
            int idx = i * 256 + tid;
            int r = idx >> 2, c = (idx & 3) * 4;
            cpa16(&Bs[buf * GB_BUF + r * GA_STR + c],
                  Bm + (size_t)(bn + r) * K + kt + c);
        }
    };

    load_tile(0, 0);
    cpa_commit();

    for (int t = 0; t < NT; t++) {
        int buf = t & 1;
        if (t + 1 < NT) load_tile((t + 1) << 4, buf ^ 1);
        cpa_commit();
        cpa_wait<1>();
        __syncthreads();

        const float* Ab = As + buf * GA_BUF;
        const float* Bb = Bs + buf * GB_BUF;

#pragma unroll
        for (int kk = 0; kk < 16; kk += 8) {
            unsigned a[4][4], b[8][2];
            const int c = kk + (lane & 3);
#pragma unroll
            for (int mi = 0; mi < 4; mi++) {
                int r = wm * 64 + mi * 16 + (lane >> 2);
                a[mi][0] = ldtf(Ab[r * GA_STR + c]);
                a[mi][1] = ldtf(Ab[(r + 8) * GA_STR + c]);
                a[mi][2] = ldtf(Ab[r * GA_STR + c + 4]);
                a[mi][3] = ldtf(Ab[(r + 8) * GA_STR + c + 4]);
            }
#pragma unroll
            for (int ni = 0; ni < 8; ni++) {
                int rB = wn * 64 + ni * 8 + (lane >> 2);
                b[ni][0] = ldtf(Bb[rB * GA_STR + c]);
                b[ni][1] = ldtf(Bb[rB * GA_STR + c + 4]);
            }
#pragma unroll
            for (int mi = 0; mi < 4; mi++)
#pragma unroll
                for (int ni = 0; ni < 8; ni++)
                    mma8(acc[mi][ni], a[mi], b[ni]);
        }
        __syncthreads();
    }

    // Epilogue
#pragma unroll
    for (int mi = 0; mi < 4; mi++) {
#pragma unroll
        for (int ni = 0; ni < 8; ni++) {
            int row = bm + wm * 64 + mi * 16 + (lane >> 2);
            int col = bn + wn * 64 + ni * 8 + 2 * (lane & 3);
#pragma unroll
            for (int half = 0; half < 2; half++) {
                int r = row + half * 8;
                float v0 = acc[mi][ni][half * 2 + 0] + bias[col];
                float v1 = acc[mi][ni][half * 2 + 1] + bias[col + 1];
                if (MODE == 0) {
                    C[(size_t)r * N + col]     = v0;
                    C[(size_t)r * N + col + 1] = v1;
                } else {
                    int which = col >> 10;          // 0=q,1=k,2=v
                    int cc = col & 1023;
                    int hh = cc >> 6, dd = cc & 63;
                    int bi = r >> 11, tt = r & 2047;
                    if (which == 0) { v0 *= 0.125f; v1 *= 0.125f; }  // 1/sqrt(64)
                    float* dst = (which == 0) ? qb : ((which == 1) ? kb : vb);
                    size_t off = ((((size_t)bi * NH + hh) * TS) + tt) * DKH + dd;
                    dst[off]     = v0;
                    dst[off + 1] = v1;
                }
            }
        }
    }
}

// ---------------------------------------------------------------------------
// Flash attention v2: block = 128 q-rows x (head, batch), 128 threads
// (4 warps, 32 q-rows each). K/V tiles of 64 keys, double-buffered cp.async.
// Q rounded RNA at fill; K/V rounded RNA at fragment load; P rounded at store.
// Q/K/S smem stride 76, V stride 72 (both mma access patterns conflict-free).
// ---------------------------------------------------------------------------
#define QS_STRIDE 76
#define VS_STRIDE 72
#define KBUF (64 * QS_STRIDE)
#define VBUF (64 * VS_STRIDE)

__global__ void __launch_bounds__(128, 1) attn_kernel(
    const float* __restrict__ qg, const float* __restrict__ kg,
    const float* __restrict__ vg, float* __restrict__ yg)
{
    extern __shared__ float sm[];
    float* Qs = sm;                    // 128*76
    float* Ss = Qs + 128 * QS_STRIDE;  // 128*76
    float* Ks = Ss + 128 * QS_STRIDE;  // 2 x 64*76
    float* Vs = Ks + 2 * KBUF;         // 2 x 64*72

    const int tid  = threadIdx.x;
    const int lane = tid & 31;
    const int warp = tid >> 5;
    const int qt = blockIdx.x, h = blockIdx.y, b = blockIdx.z;
    const size_t headbase = (((size_t)b * NH + h) * TS) * DKH;
    const int mb = warp * 32;

    // Load Q tile (pre-scaled by 1/sqrt(dk)); RNA-round once here.
    {
        const float* qp = qg + headbase + (size_t)qt * 128 * DKH;
#pragma unroll
        for (int i = 0; i < 16; i++) {
            int idx = i * 128 + tid;            // 2048 float4s
            int r = idx >> 4, c = (idx & 15) * 4;
            float4 v4 = *(const float4*)(qp + r * 64 + c);
            Qs[r * QS_STRIDE + c + 0] = tfr(v4.x);
            Qs[r * QS_STRIDE + c + 1] = tfr(v4.y);
            Qs[r * QS_STRIDE + c + 2] = tfr(v4.z);
            Qs[r * QS_STRIDE + c + 3] = tfr(v4.w);
        }
    }

    float accO[2][8][4];
#pragma unroll
    for (int mi = 0; mi < 2; mi++)
#pragma unroll
        for (int nf = 0; nf < 8; nf++)
#pragma unroll
            for (int q = 0; q < 4; q++) accO[mi][nf][q] = 0.0f;
    float mrow[2][2] = {{-1e30f, -1e30f}, {-1e30f, -1e30f}};
    float lrow[2][2] = {{0.0f, 0.0f}, {0.0f, 0.0f}};

    auto load_kv = [&](int j, int buf) {
        const float* kp = kg + headbase + (size_t)j * 64 * DKH;
        const float* vp = vg + headbase + (size_t)j * 64 * DKH;
#pragma unroll
        for (int i = 0; i < 8; i++) {
            int idx = i * 128 + tid;            // 1024 float4s each
            int r = idx >> 4, c = (idx & 15) * 4;
            cpa16(&Ks[buf * KBUF + r * QS_STRIDE + c], kp + r * 64 + c);
            cpa16(&Vs[buf * VBUF + r * VS_STRIDE + c], vp + r * 64 + c);
        }
    };

    load_kv(0, 0);
    cpa_commit();

    for (int j = 0; j < TS / 64; j++) {
        int buf = j & 1;
        if (j + 1 < TS / 64) load_kv(j + 1, buf ^ 1);
        cpa_commit();
        cpa_wait<1>();
        __syncthreads();   // tile j resident; also covers Q on j=0

        const float* Kb = Ks + buf * KBUF;
        const float* Vb = Vs + buf * VBUF;

        // S = Q @ K^T  (warp's 32 rows x 64 keys)
        float accS[2][8][4];
#pragma unroll
        for (int mi = 0; mi < 2; mi++)
#pragma unroll
            for (int nf = 0; nf < 8; nf++)
#pragma unroll
                for (int q = 0; q < 4; q++) accS[mi][nf][q] = 0.0f;

#pragma unroll
        for (int kk = 0; kk < 64; kk += 8) {
            const int c = kk + (lane & 3);
            unsigned a[2][4];
#pragma unroll
            for (int mi = 0; mi < 2; mi++) {
                int r = mb + mi * 16 + (lane >> 2);
                a[mi][0] = __float_as_uint(Qs[r * QS_STRIDE + c]);
                a[mi][1] = __float_as_uint(Qs[(r + 8) * QS_STRIDE + c]);
                a[mi][2] = __float_as_uint(Qs[r * QS_STRIDE + c + 4]);
                a[mi][3] = __float_as_uint(Qs[(r + 8) * QS_STRIDE + c + 4]);
            }
#pragma unroll
            for (int nf = 0; nf < 8; nf++) {
                unsigned bf[2];
                int kr = nf * 8 + (lane >> 2);
                bf[0] = ldtf(Kb[kr * QS_STRIDE + c]);
                bf[1] = ldtf(Kb[kr * QS_STRIDE + c + 4]);
                mma8(accS[0][nf], a[0], bf);
                mma8(accS[1][nf], a[1], bf);
            }
        }

        // Online softmax per 16-row chunk (2 rows/thread per chunk)
#pragma unroll
        for (int mi = 0; mi < 2; mi++) {
            float tm0 = -1e30f, tm1 = -1e30f;
#pragma unroll
            for (int nf = 0; nf < 8; nf++) {
                tm0 = fmaxf(tm0, fmaxf(accS[mi][nf][0], accS[mi][nf][1]));
                tm1 = fmaxf(tm1, fmaxf(accS[mi][nf][2], accS[mi][nf][3]));
            }
            tm0 = fmaxf(tm0, __shfl_xor_sync(0xffffffffu, tm0, 1));
            tm0 = fmaxf(tm0, __shfl_xor_sync(0xffffffffu, tm0, 2));
            tm1 = fmaxf(tm1, __shfl_xor_sync(0xffffffffu, tm1, 1));
            tm1 = fmaxf(tm1, __shfl_xor_sync(0xffffffffu, tm1, 2));

            float mn0 = fmaxf(mrow[mi][0], tm0), mn1 = fmaxf(mrow[mi][1], tm1);
            float al0 = __expf(mrow[mi][0] - mn0), al1 = __expf(mrow[mi][1] - mn1);

            float s0 = 0.0f, s1 = 0.0f;
#pragma unroll
            for (int nf = 0; nf < 8; nf++) {
                accS[mi][nf][0] = __expf(accS[mi][nf][0] - mn0);
                accS[mi][nf][1] = __expf(accS[mi][nf][1] - mn0);
                accS[mi][nf][2] = __expf(accS[mi][nf][2] - mn1);
                accS[mi][nf][3] = __expf(accS[mi][nf][3] - mn1);
                s0 += accS[mi][nf][0] + accS[mi][nf][1];
                s1 += accS[mi][nf][2] + accS[mi][nf][3];
            }
            s0 += __shfl_xor_sync(0xffffffffu, s0, 1);
            s0 += __shfl_xor_sync(0xffffffffu, s0, 2);
            s1 += __shfl_xor_sync(0xffffffffu, s1, 1);
            s1 += __shfl_xor_sync(0xffffffffu, s1, 2);

            lrow[mi][0] = lrow[mi][0] * al0 + s0;
            lrow[mi][1] = lrow[mi][1] * al1 + s1;
            mrow[mi][0] = mn0; mrow[mi][1] = mn1;

#pragma unroll
            for (int nf = 0; nf < 8; nf++) {
                accO[mi][nf][0] *= al0; accO[mi][nf][1] *= al0;
                accO[mi][nf][2] *= al1; accO[mi][nf][3] *= al1;
            }

            // Store P (RNA tf32-rounded) to warp-private rows of Ss
            int r0 = mb + mi * 16 + (lane >> 2);
#pragma unroll
            for (int nf = 0; nf < 8; nf++) {
                int c0 = nf * 8 + 2 * (lane & 3);
                Ss[r0 * QS_STRIDE + c0]           = tfr(accS[mi][nf][0]);
                Ss[r0 * QS_STRIDE + c0 + 1]       = tfr(accS[mi][nf][1]);
                Ss[(r0 + 8) * QS_STRIDE + c0]     = tfr(accS[mi][nf][2]);
                Ss[(r0 + 8) * QS_STRIDE + c0 + 1] = tfr(accS[mi][nf][3]);
            }
        }
        __syncwarp();  // warp-local P round-trip only

        // O += P @ V
#pragma unroll
        for (int kk = 0; kk < 64; kk += 8) {
            const int c = kk + (lane & 3);
            unsigned a[2][4];
#pragma unroll
            for (int mi = 0; mi < 2; mi++) {
                int r = mb + mi * 16 + (lane >> 2);
                a[mi][0] = __float_as_uint(Ss[r * QS_STRIDE + c]);
                a[mi][1] = __float_as_uint(Ss[(r + 8) * QS_STRIDE + c]);
                a[mi][2] = __float_as_uint(Ss[r * QS_STRIDE + c + 4]);
                a[mi][3] = __float_as_uint(Ss[(r + 8) * QS_STRIDE + c + 4]);
            }
#pragma unroll
            for (int nf = 0; nf < 8; nf++) {
                unsigned bf[2];
                int vc = nf * 8 + (lane >> 2);
                bf[0] = ldtf(Vb[(kk + (lane & 3)) * VS_STRIDE + vc]);
                bf[1] = ldtf(Vb[(kk + (lane & 3) + 4) * VS_STRIDE + vc]);
                mma8(accO[0][nf], a[0], bf);
                mma8(accO[1][nf], a[1], bf);
            }
        }
        __syncthreads();  // all readers of buf done before its next overwrite
    }

    // Normalize and write to y in [B, T, C] layout
#pragma unroll
    for (int mi = 0; mi < 2; mi++) {
        float inv0 = 1.0f / lrow[mi][0], inv1 = 1.0f / lrow[mi][1];
        int r0 = mb + mi * 16 + (lane >> 2);
        size_t t0 = (size_t)b * TS + (size_t)qt * 128 + r0;
#pragma unroll
        for (int nf = 0; nf < 8; nf++) {
            int c0 = nf * 8 + 2 * (lane & 3);
            float2 o0 = make_float2(accO[mi][nf][0] * inv0, accO[mi][nf][1] * inv0);
            *(float2*)(yg + t0 * DM + h * 64 + c0) = o0;
            float2 o1 = make_float2(accO[mi][nf][2] * inv1, accO[mi][nf][3] * inv1);
            *(float2*)(yg + (t0 + 8) * DM + h * 64 + c0) = o1;
        }
    }
}

// ---------------------------------------------------------------------------
extern "C" void kernel_launch(void* const* d_in, const int* in_sizes, int n_in,
                              void* d_out, int out_size) {
    const float* x      = (const float*)d_in[0];
    const float* w_attn = (const float*)d_in[1];
    const float* b_attn = (const float*)d_in[2];
    const float* w_proj = (const float*)d_in[3];
    const float* b_proj = (const float*)d_in[4];
    float* out = (float*)d_out;

    float *qp, *kp, *vp, *yp;
    cudaGetSymbolAddress((void**)&qp, g_q);
    cudaGetSymbolAddress((void**)&kp, g_k);
    cudaGetSymbolAddress((void**)&vp, g_v);
    cudaGetSymbolAddress((void**)&yp, g_y);

    const int smem_gemm = 2 * (GA_BUF + GB_BUF) * 4;                 // 61440 B
    const int smem_attn = (2 * 128 * QS_STRIDE + 2 * KBUF + 2 * VBUF) * 4;  // 153600 B
    cudaFuncSetAttribute(gemm_tn<1>, cudaFuncAttributeMaxDynamicSharedMemorySize,
                         smem_gemm);
    cudaFuncSetAttribute(gemm_tn<0>, cudaFuncAttributeMaxDynamicSharedMemorySize,
                         smem_gemm);
    cudaFuncSetAttribute(attn_kernel, cudaFuncAttributeMaxDynamicSharedMemorySize,
                         smem_attn);

    // 1) QKV projection + scatter to [B,H,T,dk] (Q pre-scaled)
    gemm_tn<1><<<dim3(3 * DM / 256, MTOT / 128), 256, smem_gemm>>>(
        x, w_attn, b_attn, nullptr, qp, kp, vp, MTOT, 3 * DM, DM);

    // 2) Flash attention -> y [B,T,C]
    attn_kernel<<<dim3(TS / 128, NH, BB), 128, smem_attn>>>(qp, kp, vp, yp);

    // 3) Output projection -> d_out
    gemm_tn<0><<<dim3(DM / 256, MTOT / 128), 256, smem_gemm>>>(
        yp, w_proj, b_proj, out, nullptr, nullptr, nullptr, MTOT, DM, DM);
}

// round 8
// speedup vs baseline: 1.6018x; 1.6018x over previous
#include <cuda_runtime.h>
#include <cstdint>

#define DM   1024
#define NH   16
#define DKH  64
#define BB   4
#define TS   2048
#define MTOT (BB*TS)        // 8192
#define ELEMS (MTOT*DM)     // 8388608

// Scratch (static device memory — no allocation allowed)
__device__ float g_q[ELEMS];
__device__ float g_k[ELEMS];
__device__ float g_v[ELEMS];
__device__ float g_y[ELEMS];

// RNA tf32 rounding (value-preserving float form)
__device__ __forceinline__ float tfr(float f) {
    unsigned u;
    asm("cvt.rna.tf32.f32 %0, %1;" : "=r"(u) : "f"(f));
    return __uint_as_float(u);
}

__device__ __forceinline__ void mma8(float* d, const unsigned* a, const unsigned* b) {
    asm volatile(
        "mma.sync.aligned.m16n8k8.row.col.f32.tf32.tf32.f32 "
        "{%0,%1,%2,%3}, {%4,%5,%6,%7}, {%8,%9}, {%0,%1,%2,%3};\n"
        : "+f"(d[0]), "+f"(d[1]), "+f"(d[2]), "+f"(d[3])
        : "r"(a[0]), "r"(a[1]), "r"(a[2]), "r"(a[3]), "r"(b[0]), "r"(b[1]));
}

__device__ __forceinline__ void cpa16(void* smem, const void* g) {
    unsigned s = (unsigned)__cvta_generic_to_shared(smem);
    asm volatile("cp.async.cg.shared.global [%0], [%1], 16;" :: "r"(s), "l"(g));
}
__device__ __forceinline__ void cpa_commit() {
    asm volatile("cp.async.commit_group;");
}
template <int N>
__device__ __forceinline__ void cpa_wait() {
    asm volatile("cp.async.wait_group %0;" :: "n"(N));
}

// ---------------------------------------------------------------------------
// C[M,N] = A[M,K] @ B[N,K]^T + bias.  MODE 0: plain row-major write.
// MODE 1: scatter into q/k/v [B,H,T,64], values tf32-pre-rounded; Q *0.125.
// BM=BN=128, BK=16; 128 threads = 4 warps, warp tile 64x64.
// Single-buffer LDG->tfr->STS (RNA rounding at fill). 2 CTAs/SM target.
// ---------------------------------------------------------------------------
#define GA_STR 20

template <int MODE>
__global__ void __launch_bounds__(128, 2) gemm_tn(
    const float* __restrict__ A, const float* __restrict__ Bm,
    const float* __restrict__ bias, float* __restrict__ C,
    float* __restrict__ qb, float* __restrict__ kb, float* __restrict__ vb,
    int M, int N, int K)
{
    __shared__ float As[128][GA_STR];
    __shared__ float Bs[128][GA_STR];

    const int tid  = threadIdx.x;
    const int lane = tid & 31;
    const int warp = tid >> 5;
    const int wm = warp >> 1;     // 0..1
    const int wn = warp & 1;      // 0..1
    const int bm = blockIdx.y * 128;
    const int bn = blockIdx.x * 128;

    float acc[4][8][4];
#pragma unroll
    for (int mi = 0; mi < 4; mi++)
#pragma unroll
        for (int ni = 0; ni < 8; ni++)
#pragma unroll
            for (int q = 0; q < 4; q++) acc[mi][ni][q] = 0.0f;

    const int lr = tid >> 2;        // 0..31
    const int lc = (tid & 3) * 4;   // 0,4,8,12

    for (int kt = 0; kt < K; kt += 16) {
        // 512 float4 per array / 128 thr = 4 each; independent LDGs for MLP
        float4 av[4], bv[4];
#pragma unroll
        for (int i = 0; i < 4; i++) {
            int r = lr + i * 32;
            av[i] = *(const float4*)(A + (size_t)(bm + r) * K + kt + lc);
            bv[i] = *(const float4*)(Bm + (size_t)(bn + r) * K + kt + lc);
        }
#pragma unroll
        for (int i = 0; i < 4; i++) {
            int r = lr + i * 32;
            As[r][lc + 0] = tfr(av[i].x); As[r][lc + 1] = tfr(av[i].y);
            As[r][lc + 2] = tfr(av[i].z); As[r][lc + 3] = tfr(av[i].w);
            Bs[r][lc + 0] = tfr(bv[i].x); Bs[r][lc + 1] = tfr(bv[i].y);
            Bs[r][lc + 2] = tfr(bv[i].z); Bs[r][lc + 3] = tfr(bv[i].w);
        }
        __syncthreads();

#pragma unroll
        for (int kk = 0; kk < 16; kk += 8) {
            unsigned a[4][4], b[8][2];
            const int c = kk + (lane & 3);
#pragma unroll
            for (int mi = 0; mi < 4; mi++) {
                int r = wm * 64 + mi * 16 + (lane >> 2);
                a[mi][0] = __float_as_uint(As[r][c]);
                a[mi][1] = __float_as_uint(As[r + 8][c]);
                a[mi][2] = __float_as_uint(As[r][c + 4]);
                a[mi][3] = __float_as_uint(As[r + 8][c + 4]);
            }
#pragma unroll
            for (int ni = 0; ni < 8; ni++) {
                int rB = wn * 64 + ni * 8 + (lane >> 2);
                b[ni][0] = __float_as_uint(Bs[rB][c]);
                b[ni][1] = __float_as_uint(Bs[rB][c + 4]);
            }
#pragma unroll
            for (int mi = 0; mi < 4; mi++)
#pragma unroll
                for (int ni = 0; ni < 8; ni++)
                    mma8(acc[mi][ni], a[mi], b[ni]);
        }
        __syncthreads();
    }

    // Epilogue
#pragma unroll
    for (int mi = 0; mi < 4; mi++) {
#pragma unroll
        for (int ni = 0; ni < 8; ni++) {
            int row = bm + wm * 64 + mi * 16 + (lane >> 2);
            int col = bn + wn * 64 + ni * 8 + 2 * (lane & 3);
#pragma unroll
            for (int half = 0; half < 2; half++) {
                int r = row + half * 8;
                float v0 = acc[mi][ni][half * 2 + 0] + bias[col];
                float v1 = acc[mi][ni][half * 2 + 1] + bias[col + 1];
                if (MODE == 0) {
                    C[(size_t)r * N + col]     = v0;
                    C[(size_t)r * N + col + 1] = v1;
                } else {
                    int which = col >> 10;          // 0=q,1=k,2=v
                    int cc = col & 1023;
                    int hh = cc >> 6, dd = cc & 63;
                    int bi = r >> 11, tt = r & 2047;
                    // Pre-round to tf32 (RNA) so attention needs no cvt:
                    // HMMA truncation of an exact-tf32 value is the identity.
                    v0 = tfr(v0); v1 = tfr(v1);
                    if (which == 0) { v0 *= 0.125f; v1 *= 0.125f; }  // exact
                    float* dst = (which == 0) ? qb : ((which == 1) ? kb : vb);
                    size_t off = ((((size_t)bi * NH + hh) * TS) + tt) * DKH + dd;
                    dst[off]     = v0;
                    dst[off + 1] = v1;
                }
            }
        }
    }
}

// ---------------------------------------------------------------------------
// Flash attention: block = 128 q-rows x (head, batch), 256 threads
// (8 warps x 16 q-rows). K/V tiles of 64 keys, double-buffered cp.async.
// Q/K/V arrive pre-rounded to tf32 (QKV epilogue) -> no cvt anywhere here.
// Q/K/S smem stride 76, V stride 72 (both mma access patterns conflict-free).
// ---------------------------------------------------------------------------
#define QS_STRIDE 76
#define VS_STRIDE 72
#define KBUF (64 * QS_STRIDE)
#define VBUF (64 * VS_STRIDE)

__global__ void __launch_bounds__(256, 1) attn_kernel(
    const float* __restrict__ qg, const float* __restrict__ kg,
    const float* __restrict__ vg, float* __restrict__ yg)
{
    extern __shared__ float sm[];
    float* Qs = sm;                    // 128*76
    float* Ss = Qs + 128 * QS_STRIDE;  // 128*76
    float* Ks = Ss + 128 * QS_STRIDE;  // 2 x 64*76
    float* Vs = Ks + 2 * KBUF;         // 2 x 64*72

    const int tid  = threadIdx.x;
    const int lane = tid & 31;
    const int warp = tid >> 5;
    const int qt = blockIdx.x, h = blockIdx.y, b = blockIdx.z;
    const size_t headbase = (((size_t)b * NH + h) * TS) * DKH;
    const int mb = warp * 16;

    // Load Q tile 128x64 (pre-scaled, pre-rounded): 2048 float4 / 256 thr
    {
        const float* qp = qg + headbase + (size_t)qt * 128 * DKH;
#pragma unroll
        for (int i = 0; i < 8; i++) {
            int idx = i * 256 + tid;
            int r = idx >> 4, c = (idx & 15) * 4;
            *(float4*)&Qs[r * QS_STRIDE + c] = *(const float4*)(qp + r * 64 + c);
        }
    }

    float accO[8][4];
#pragma unroll
    for (int nf = 0; nf < 8; nf++)
#pragma unroll
        for (int q = 0; q < 4; q++) accO[nf][q] = 0.0f;
    float mrow[2] = {-1e30f, -1e30f};
    float lrow[2] = {0.0f, 0.0f};

    auto load_kv = [&](int j, int buf) {
        const float* kp = kg + headbase + (size_t)j * 64 * DKH;
        const float* vp = vg + headbase + (size_t)j * 64 * DKH;
#pragma unroll
        for (int i = 0; i < 4; i++) {
            int idx = i * 256 + tid;            // 1024 float4s each
            int r = idx >> 4, c = (idx & 15) * 4;
            cpa16(&Ks[buf * KBUF + r * QS_STRIDE + c], kp + r * 64 + c);
            cpa16(&Vs[buf * VBUF + r * VS_STRIDE + c], vp + r * 64 + c);
        }
    };

    load_kv(0, 0);
    cpa_commit();

    for (int j = 0; j < TS / 64; j++) {
        int buf = j & 1;
        if (j + 1 < TS / 64) load_kv(j + 1, buf ^ 1);
        cpa_commit();
        cpa_wait<1>();
        __syncthreads();   // tile j resident; also covers Q on j=0

        const float* Kb = Ks + buf * KBUF;
        const float* Vb = Vs + buf * VBUF;

        // S = Q @ K^T  (warp's 16 rows x 64 keys)
        float accS[8][4];
#pragma unroll
        for (int nf = 0; nf < 8; nf++)
#pragma unroll
            for (int q = 0; q < 4; q++) accS[nf][q] = 0.0f;

#pragma unroll
        for (int kk = 0; kk < 64; kk += 8) {
            const int c = kk + (lane & 3);
            unsigned a[4];
            int r = mb + (lane >> 2);
            a[0] = __float_as_uint(Qs[r * QS_STRIDE + c]);
            a[1] = __float_as_uint(Qs[(r + 8) * QS_STRIDE + c]);
            a[2] = __float_as_uint(Qs[r * QS_STRIDE + c + 4]);
            a[3] = __float_as_uint(Qs[(r + 8) * QS_STRIDE + c + 4]);
#pragma unroll
            for (int nf = 0; nf < 8; nf++) {
                unsigned bf[2];
                int kr = nf * 8 + (lane >> 2);
                bf[0] = __float_as_uint(Kb[kr * QS_STRIDE + c]);
                bf[1] = __float_as_uint(Kb[kr * QS_STRIDE + c + 4]);
                mma8(accS[nf], a, bf);
            }
        }

        // Online softmax (2 rows/thread: r0 = mb + lane/4, r1 = r0 + 8)
        float tm0 = -1e30f, tm1 = -1e30f;
#pragma unroll
        for (int nf = 0; nf < 8; nf++) {
            tm0 = fmaxf(tm0, fmaxf(accS[nf][0], accS[nf][1]));
            tm1 = fmaxf(tm1, fmaxf(accS[nf][2], accS[nf][3]));
        }
        tm0 = fmaxf(tm0, __shfl_xor_sync(0xffffffffu, tm0, 1));
        tm0 = fmaxf(tm0, __shfl_xor_sync(0xffffffffu, tm0, 2));
        tm1 = fmaxf(tm1, __shfl_xor_sync(0xffffffffu, tm1, 1));
        tm1 = fmaxf(tm1, __shfl_xor_sync(0xffffffffu, tm1, 2));

        float mn0 = fmaxf(mrow[0], tm0), mn1 = fmaxf(mrow[1], tm1);
        float al0 = __expf(mrow[0] - mn0), al1 = __expf(mrow[1] - mn1);

        float s0 = 0.0f, s1 = 0.0f;
#pragma unroll
        for (int nf = 0; nf < 8; nf++) {
            accS[nf][0] = __expf(accS[nf][0] - mn0);
            accS[nf][1] = __expf(accS[nf][1] - mn0);
            accS[nf][2] = __expf(accS[nf][2] - mn1);
            accS[nf][3] = __expf(accS[nf][3] - mn1);
            s0 += accS[nf][0] + accS[nf][1];
            s1 += accS[nf][2] + accS[nf][3];
        }
        s0 += __shfl_xor_sync(0xffffffffu, s0, 1);
        s0 += __shfl_xor_sync(0xffffffffu, s0, 2);
        s1 += __shfl_xor_sync(0xffffffffu, s1, 1);
        s1 += __shfl_xor_sync(0xffffffffu, s1, 2);

        lrow[0] = lrow[0] * al0 + s0;
        lrow[1] = lrow[1] * al1 + s1;
        mrow[0] = mn0; mrow[1] = mn1;

#pragma unroll
        for (int nf = 0; nf < 8; nf++) {
            accO[nf][0] *= al0; accO[nf][1] *= al0;
            accO[nf][2] *= al1; accO[nf][3] *= al1;
        }

        // Store P (RNA tf32-rounded) to warp-private rows of Ss
        {
            int r0 = mb + (lane >> 2);
#pragma unroll
            for (int nf = 0; nf < 8; nf++) {
                int c0 = nf * 8 + 2 * (lane & 3);
                Ss[r0 * QS_STRIDE + c0]           = tfr(accS[nf][0]);
                Ss[r0 * QS_STRIDE + c0 + 1]       = tfr(accS[nf][1]);
                Ss[(r0 + 8) * QS_STRIDE + c0]     = tfr(accS[nf][2]);
                Ss[(r0 + 8) * QS_STRIDE + c0 + 1] = tfr(accS[nf][3]);
            }
        }
        __syncwarp();  // warp-local P round-trip only

        // O += P @ V
#pragma unroll
        for (int kk = 0; kk < 64; kk += 8) {
            const int c = kk + (lane & 3);
            unsigned a[4];
            int r = mb + (lane >> 2);
            a[0] = __float_as_uint(Ss[r * QS_STRIDE + c]);
            a[1] = __float_as_uint(Ss[(r + 8) * QS_STRIDE + c]);
            a[2] = __float_as_uint(Ss[r * QS_STRIDE + c + 4]);
            a[3] = __float_as_uint(Ss[(r + 8) * QS_STRIDE + c + 4]);
#pragma unroll
            for (int nf = 0; nf < 8; nf++) {
                unsigned bf[2];
                int vc = nf * 8 + (lane >> 2);
                bf[0] = __float_as_uint(Vb[(kk + (lane & 3)) * VS_STRIDE + vc]);
                bf[1] = __float_as_uint(Vb[(kk + (lane & 3) + 4) * VS_STRIDE + vc]);
                mma8(accO[nf], a, bf);
            }
        }
        __syncthreads();  // all warps done with buf before its next overwrite
    }

    // Normalize and write to y in [B, T, C] layout
    float inv0 = 1.0f / lrow[0], inv1 = 1.0f / lrow[1];
    int r0 = mb + (lane >> 2);
    size_t t0 = (size_t)b * TS + (size_t)qt * 128 + r0;
#pragma unroll
    for (int nf = 0; nf < 8; nf++) {
        int c0 = nf * 8 + 2 * (lane & 3);
        float2 o0 = make_float2(accO[nf][0] * inv0, accO[nf][1] * inv0);
        *(float2*)(yg + t0 * DM + h * 64 + c0) = o0;
        float2 o1 = make_float2(accO[nf][2] * inv1, accO[nf][3] * inv1);
        *(float2*)(yg + (t0 + 8) * DM + h * 64 + c0) = o1;
    }
}

// ---------------------------------------------------------------------------
extern "C" void kernel_launch(void* const* d_in, const int* in_sizes, int n_in,
                              void* d_out, int out_size) {
    const float* x      = (const float*)d_in[0];
    const float* w_attn = (const float*)d_in[1];
    const float* b_attn = (const float*)d_in[2];
    const float* w_proj = (const float*)d_in[3];
    const float* b_proj = (const float*)d_in[4];
    float* out = (float*)d_out;

    float *qp, *kp, *vp, *yp;
    cudaGetSymbolAddress((void**)&qp, g_q);
    cudaGetSymbolAddress((void**)&kp, g_k);
    cudaGetSymbolAddress((void**)&vp, g_v);
    cudaGetSymbolAddress((void**)&yp, g_y);

    const int smem_attn = (2 * 128 * QS_STRIDE + 2 * KBUF + 2 * VBUF) * 4;  // 153600 B
    cudaFuncSetAttribute(attn_kernel, cudaFuncAttributeMaxDynamicSharedMemorySize,
                         smem_attn);

    // 1) QKV projection + scatter to [B,H,T,dk] (pre-rounded, Q pre-scaled)
    gemm_tn<1><<<dim3(3 * DM / 128, MTOT / 128), 128>>>(
        x, w_attn, b_attn, nullptr, qp, kp, vp, MTOT, 3 * DM, DM);

    // 2) Flash attention -> y [B,T,C]
    attn_kernel<<<dim3(TS / 128, NH, BB), 256, smem_attn>>>(qp, kp, vp, yp);

    // 3) Output projection -> d_out
    gemm_tn<0><<<dim3(DM / 128, MTOT / 128), 128>>>(
        yp, w_proj, b_proj, out, nullptr, nullptr, nullptr, MTOT, DM, DM);
}

// round 10
// speedup vs baseline: 2.9952x; 1.8699x over previous
#include <cuda_runtime.h>
#include <cuda_fp16.h>
#include <cstdint>

#define DM   1024
#define NH   16
#define DKH  64
#define BB   4
#define TS   2048
#define MTOT (BB*TS)        // 8192
#define ELEMS (MTOT*DM)     // 8388608

// Scratch (static device memory — no allocation allowed)
__device__ __half g_q[ELEMS];          // [B,H,T,dk] fp16, pre-scaled
__device__ __half g_k[ELEMS];          // [B,H,T,dk] fp16
__device__ __half g_v[ELEMS];          // [B,H,dk,T] fp16 (transposed per head)
__device__ __half g_y[ELEMS];          // [B,T,C] fp16
__device__ __half g_xh[ELEMS];         // x  -> fp16
__device__ __half g_wah[3 * DM * DM];  // w_attn -> fp16
__device__ __half g_wph[DM * DM];      // w_proj -> fp16

__device__ __forceinline__ void mma16(float* d, const unsigned* a, const unsigned* b) {
    asm volatile(
        "mma.sync.aligned.m16n8k16.row.col.f32.f16.f16.f32 "
        "{%0,%1,%2,%3}, {%4,%5,%6,%7}, {%8,%9}, {%0,%1,%2,%3};\n"
        : "+f"(d[0]), "+f"(d[1]), "+f"(d[2]), "+f"(d[3])
        : "r"(a[0]), "r"(a[1]), "r"(a[2]), "r"(a[3]), "r"(b[0]), "r"(b[1]));
}

__device__ __forceinline__ void cpa16(void* smem, const void* g) {
    unsigned s = (unsigned)__cvta_generic_to_shared(smem);
    asm volatile("cp.async.cg.shared.global [%0], [%1], 16;" :: "r"(s), "l"(g));
}
__device__ __forceinline__ void cpa_commit() {
    asm volatile("cp.async.commit_group;");
}
template <int N>
__device__ __forceinline__ void cpa_wait() {
    asm volatile("cp.async.wait_group %0;" :: "n"(N));
}

// fp32 -> fp16 (RN) bulk convert
__global__ void f2h(const float2* __restrict__ s, __half2* __restrict__ d, int n2) {
    int i = blockIdx.x * blockDim.x + threadIdx.x;
    if (i < n2) { float2 v = s[i]; d[i] = __floats2half2_rn(v.x, v.y); }
}

// ---------------------------------------------------------------------------
// fp16 GEMM: C[M,N] = A[M,K] @ B[N,K]^T + bias (A,B fp16; accum fp32).
// BM=BN=128, BK=32 (2 k16 planes); 128 threads = 4 warps, warp tile 64x64.
// 3-stage 16B-cp.async ring. smem plane rows: 8 data u32 + 4 pad (stride 12)
// -> fragment LDS bank-conflict-free, 16B-aligned rows. 2 CTAs/SM.
// MODE 0: fp32 row-major + bias.  MODE 1: fp16 q/k [B,H,T,64] (Q*0.125) and
// v transposed [B,H,64,T].
// ---------------------------------------------------------------------------
#define PLANE  1536                   // 128 rows * 12 u32
#define STAGEU (4 * PLANE)            // A(2 planes) + B(2 planes)
#define GSTG   3
#define GEMM_SMEM (GSTG * STAGEU * 4) // 73728 B

template <int MODE>
__global__ void __launch_bounds__(128, 2) gemm_h(
    const __half* __restrict__ A, const __half* __restrict__ Bm,
    const float* __restrict__ bias, float* __restrict__ C,
    __half* __restrict__ qb, __half* __restrict__ kb, __half* __restrict__ vb,
    int M, int N, int K)
{
    extern __shared__ unsigned smu[];

    const int tid  = threadIdx.x;
    const int lane = tid & 31;
    const int warp = tid >> 5;
    const int wm = warp >> 1, wn = warp & 1;
    const int bm = blockIdx.y * 128;
    const int bn = blockIdx.x * 128;
    const int NT = K >> 5;

    float acc[4][8][4];
#pragma unroll
    for (int mi = 0; mi < 4; mi++)
#pragma unroll
        for (int ni = 0; ni < 8; ni++)
#pragma unroll
            for (int q = 0; q < 4; q++) acc[mi][ni][q] = 0.0f;

    // stage loader: 512 16B-chunks each for A and B, 8 cp.async per thread
    auto load_stage = [&](int t, int p) {
        const __half* Ag = A + (size_t)bm * K + t * 32;
        const __half* Bg = Bm + (size_t)bn * K + t * 32;
        unsigned base = p * STAGEU;
#pragma unroll
        for (int i = 0; i < 4; i++) {
            int idx = i * 128 + tid;        // 0..511
            int r = idx >> 2, ch = idx & 3;
            int pl = ch >> 1, c4 = (ch & 1) * 4;
            cpa16(&smu[base + pl * PLANE + r * 12 + c4],
                  Ag + (size_t)r * K + pl * 16 + c4 * 2);
            cpa16(&smu[base + 2 * PLANE + pl * PLANE + r * 12 + c4],
                  Bg + (size_t)r * K + pl * 16 + c4 * 2);
        }
        cpa_commit();
    };

    load_stage(0, 0); load_stage(1, 1); load_stage(2, 2);

    for (int t = 0; t < NT; t++) {
        const int p = t % 3;
        cpa_wait<2>();
        __syncthreads();
        const unsigned* Ab = smu + p * STAGEU;
        const unsigned* Bb = Ab + 2 * PLANE;
        const int c = lane & 3, lr = lane >> 2;

#pragma unroll
        for (int pl = 0; pl < 2; pl++) {
            const unsigned* Ap = Ab + pl * PLANE;
            const unsigned* Bp = Bb + pl * PLANE;
            unsigned a[4][4], b[8][2];
#pragma unroll
            for (int mi = 0; mi < 4; mi++) {
                int r = wm * 64 + mi * 16 + lr;
                a[mi][0] = Ap[r * 12 + c];
                a[mi][1] = Ap[(r + 8) * 12 + c];
                a[mi][2] = Ap[r * 12 + c + 4];
                a[mi][3] = Ap[(r + 8) * 12 + c + 4];
            }
#pragma unroll
            for (int ni = 0; ni < 8; ni++) {
                int rB = wn * 64 + ni * 8 + lr;
                b[ni][0] = Bp[rB * 12 + c];
                b[ni][1] = Bp[rB * 12 + c + 4];
            }
#pragma unroll
            for (int mi = 0; mi < 4; mi++)
#pragma unroll
                for (int ni = 0; ni < 8; ni++)
                    mma16(acc[mi][ni], a[mi], b[ni]);
        }
        __syncthreads();
        if (t + 3 < NT) load_stage(t + 3, p);
    }

    // Epilogue
#pragma unroll
    for (int mi = 0; mi < 4; mi++) {
#pragma unroll
        for (int ni = 0; ni < 8; ni++) {
            int row = bm + wm * 64 + mi * 16 + (lane >> 2);
            int col = bn + wn * 64 + ni * 8 + 2 * (lane & 3);
#pragma unroll
            for (int hf = 0; hf < 2; hf++) {
                int r = row + hf * 8;
                float v0 = acc[mi][ni][hf * 2 + 0] + bias[col];
                float v1 = acc[mi][ni][hf * 2 + 1] + bias[col + 1];
                if (MODE == 0) {
                    *(float2*)(C + (size_t)r * N + col) = make_float2(v0, v1);
                } else {
                    int which = col >> 10;          // 0=q,1=k,2=v
                    int cc = col & 1023;
                    int hh = cc >> 6, dd = cc & 63;
                    int bi = r >> 11, tt = r & 2047;
                    if (which == 0) { v0 *= 0.125f; v1 *= 0.125f; }  // 1/sqrt(64)
                    if (which == 2) {
                        // transposed: [B,H,dk,T]
                        size_t off = (((size_t)bi * NH + hh) * DKH + dd) * TS + tt;
                        vb[off]      = __float2half_rn(v0);
                        vb[off + TS] = __float2half_rn(v1);
                    } else {
                        __half* dst = (which == 0) ? qb : kb;
                        size_t off = (((size_t)bi * NH + hh) * TS + tt) * DKH + dd;
                        *(__half2*)(dst + off) = __floats2half2_rn(v0, v1);
                    }
                }
            }
        }
    }
}

// ---------------------------------------------------------------------------
// Flash attention (fp16 operands, fp32 accum): block = 128 q-rows x (head,
// batch), 256 threads (8 warps x 16 q-rows). K/V tiles of 64 keys, double-
// buffered 16B cp.async. smem rows: 32 data u32 + 4 pad (stride 36) ->
// conflict-free fragment LDS, 16B-aligned rows. V pre-transposed in gmem.
// ---------------------------------------------------------------------------
#define AST   36
#define KBUFU (64 * AST)
#define ATTN_SMEM ((2 * 128 * AST + 4 * KBUFU) * 4)   // 73728 B

__global__ void __launch_bounds__(256, 1) attn_kernel(
    const __half* __restrict__ qg, const __half* __restrict__ kg,
    const __half* __restrict__ vg, __half* __restrict__ yg)
{
    extern __shared__ unsigned su[];
    unsigned* Qs = su;                  // 128*36
    unsigned* Ss = Qs + 128 * AST;      // 128*36
    unsigned* Ks = Ss + 128 * AST;      // 2 x 64*36
    unsigned* Vt = Ks + 2 * KBUFU;      // 2 x 64*36

    const int tid  = threadIdx.x;
    const int lane = tid & 31;
    const int warp = tid >> 5;
    const int qt = blockIdx.x, h = blockIdx.y, b = blockIdx.z;
    const size_t hb = ((size_t)b * NH + h) * TS * DKH;  // == head base for q/k/v
    const int mb = warp * 16;
    const int c = lane & 3, lr = lane >> 2;
    const int r = mb + lr;

    // Q tile 128x64 fp16: 1024 16B chunks, 4/thread
    {
        const __half* qp = qg + hb + (size_t)qt * 128 * DKH;
#pragma unroll
        for (int i = 0; i < 4; i++) {
            int idx = i * 256 + tid;
            int rr = idx >> 3, ch = idx & 7;
            cpa16(&Qs[rr * AST + ch * 4], qp + rr * 64 + ch * 8);
        }
    }

    auto load_kv = [&](int j, int buf) {
        const __half* kp = kg + hb + (size_t)j * 64 * DKH;
        const __half* vp = vg + hb + (size_t)j * 64;     // transposed rows: +d*TS
#pragma unroll
        for (int i = 0; i < 2; i++) {
            int idx = i * 256 + tid;        // 0..511
            int rr = idx >> 3, ch = idx & 7;
            cpa16(&Ks[buf * KBUFU + rr * AST + ch * 4], kp + rr * 64 + ch * 8);
            cpa16(&Vt[buf * KBUFU + rr * AST + ch * 4], vp + (size_t)rr * TS + ch * 8);
        }
    };

    load_kv(0, 0);
    cpa_commit();       // group: Q + KV0

    float accO[8][4];
#pragma unroll
    for (int nf = 0; nf < 8; nf++)
#pragma unroll
        for (int q = 0; q < 4; q++) accO[nf][q] = 0.0f;
    float mrow[2] = {-1e30f, -1e30f};
    float lrow[2] = {0.0f, 0.0f};

    for (int j = 0; j < TS / 64; j++) {
        int buf = j & 1;
        if (j + 1 < TS / 64) load_kv(j + 1, buf ^ 1);
        cpa_commit();
        cpa_wait<1>();
        __syncthreads();   // tile j (and Q on j=0) resident

        const unsigned* Kb = Ks + buf * KBUFU;
        const unsigned* Vb = Vt + buf * KBUFU;

        // S = Q @ K^T  (16 q-rows x 64 keys per warp), dim in 4 k16 chunks
        float accS[8][4];
#pragma unroll
        for (int nf = 0; nf < 8; nf++)
#pragma unroll
            for (int q = 0; q < 4; q++) accS[nf][q] = 0.0f;

#pragma unroll
        for (int c16 = 0; c16 < 4; c16++) {
            const int cu = c16 * 8;
            unsigned a[4];
            a[0] = Qs[r * AST + cu + c];
            a[1] = Qs[(r + 8) * AST + cu + c];
            a[2] = Qs[r * AST + cu + c + 4];
            a[3] = Qs[(r + 8) * AST + cu + c + 4];
#pragma unroll
            for (int nf = 0; nf < 8; nf++) {
                unsigned bf[2];
                int kr = nf * 8 + lr;
                bf[0] = Kb[kr * AST + cu + c];
                bf[1] = Kb[kr * AST + cu + c + 4];
                mma16(accS[nf], a, bf);
            }
        }

        // Online softmax (2 rows/thread: r, r+8)
        float tm0 = -1e30f, tm1 = -1e30f;
#pragma unroll
        for (int nf = 0; nf < 8; nf++) {
            tm0 = fmaxf(tm0, fmaxf(accS[nf][0], accS[nf][1]));
            tm1 = fmaxf(tm1, fmaxf(accS[nf][2], accS[nf][3]));
        }
        tm0 = fmaxf(tm0, __shfl_xor_sync(0xffffffffu, tm0, 1));
        tm0 = fmaxf(tm0, __shfl_xor_sync(0xffffffffu, tm0, 2));
        tm1 = fmaxf(tm1, __shfl_xor_sync(0xffffffffu, tm1, 1));
        tm1 = fmaxf(tm1, __shfl_xor_sync(0xffffffffu, tm1, 2));

        float mn0 = fmaxf(mrow[0], tm0), mn1 = fmaxf(mrow[1], tm1);
        float al0 = __expf(mrow[0] - mn0), al1 = __expf(mrow[1] - mn1);

        float s0 = 0.0f, s1 = 0.0f;
#pragma unroll
        for (int nf = 0; nf < 8; nf++) {
            accS[nf][0] = __expf(accS[nf][0] - mn0);
            accS[nf][1] = __expf(accS[nf][1] - mn0);
            accS[nf][2] = __expf(accS[nf][2] - mn1);
            accS[nf][3] = __expf(accS[nf][3] - mn1);
            s0 += accS[nf][0] + accS[nf][1];
            s1 += accS[nf][2] + accS[nf][3];
        }
        s0 += __shfl_xor_sync(0xffffffffu, s0, 1);
        s0 += __shfl_xor_sync(0xffffffffu, s0, 2);
        s1 += __shfl_xor_sync(0xffffffffu, s1, 1);
        s1 += __shfl_xor_sync(0xffffffffu, s1, 2);

        lrow[0] = lrow[0] * al0 + s0;
        lrow[1] = lrow[1] * al1 + s1;
        mrow[0] = mn0; mrow[1] = mn1;

#pragma unroll
        for (int nf = 0; nf < 8; nf++) {
            accO[nf][0] *= al0; accO[nf][1] *= al0;
            accO[nf][2] *= al1; accO[nf][3] *= al1;
        }

        // P -> fp16, warp-private rows of Ss
#pragma unroll
        for (int nf = 0; nf < 8; nf++) {
            __half2 p0 = __floats2half2_rn(accS[nf][0], accS[nf][1]);
            __half2 p1 = __floats2half2_rn(accS[nf][2], accS[nf][3]);
            Ss[r * AST + nf * 4 + c]       = *(unsigned*)&p0;
            Ss[(r + 8) * AST + nf * 4 + c] = *(unsigned*)&p1;
        }
        __syncwarp();  // warp-local P round-trip only

        // O += P @ V   (keys in 4 k16 chunks; Vt rows = dims)
#pragma unroll
        for (int k16 = 0; k16 < 4; k16++) {
            const int ku = k16 * 8;
            unsigned a[4];
            a[0] = Ss[r * AST + ku + c];
            a[1] = Ss[(r + 8) * AST + ku + c];
            a[2] = Ss[r * AST + ku + c + 4];
            a[3] = Ss[(r + 8) * AST + ku + c + 4];
#pragma unroll
            for (int nf = 0; nf < 8; nf++) {
                unsigned bf[2];
                int vr = nf * 8 + lr;
                bf[0] = Vb[vr * AST + ku + c];
                bf[1] = Vb[vr * AST + ku + c + 4];
                mma16(accO[nf], a, bf);
            }
        }
        __syncthreads();  // all warps done with buf before its next overwrite
    }

    // Normalize, write y fp16 [B,T,C]
    float inv0 = 1.0f / lrow[0], inv1 = 1.0f / lrow[1];
    size_t t0 = (size_t)b * TS + (size_t)qt * 128 + r;
#pragma unroll
    for (int nf = 0; nf < 8; nf++) {
        int c0 = nf * 8 + 2 * (lane & 3);
        *(__half2*)(yg + t0 * DM + h * 64 + c0) =
            __floats2half2_rn(accO[nf][0] * inv0, accO[nf][1] * inv0);
        *(__half2*)(yg + (t0 + 8) * DM + h * 64 + c0) =
            __floats2half2_rn(accO[nf][2] * inv1, accO[nf][3] * inv1);
    }
}

// ---------------------------------------------------------------------------
extern "C" void kernel_launch(void* const* d_in, const int* in_sizes, int n_in,
                              void* d_out, int out_size) {
    const float* x      = (const float*)d_in[0];
    const float* w_attn = (const float*)d_in[1];
    const float* b_attn = (const float*)d_in[2];
    const float* w_proj = (const float*)d_in[3];
    const float* b_proj = (const float*)d_in[4];
    float* out = (float*)d_out;

    __half *qp, *kp, *vp, *yp, *xh, *wah, *wph;
    cudaGetSymbolAddress((void**)&qp, g_q);
    cudaGetSymbolAddress((void**)&kp, g_k);
    cudaGetSymbolAddress((void**)&vp, g_v);
    cudaGetSymbolAddress((void**)&yp, g_y);
    cudaGetSymbolAddress((void**)&xh, g_xh);
    cudaGetSymbolAddress((void**)&wah, g_wah);
    cudaGetSymbolAddress((void**)&wph, g_wph);

    cudaFuncSetAttribute(gemm_h<1>, cudaFuncAttributeMaxDynamicSharedMemorySize,
                         GEMM_SMEM);
    cudaFuncSetAttribute(gemm_h<0>, cudaFuncAttributeMaxDynamicSharedMemorySize,
                         GEMM_SMEM);
    cudaFuncSetAttribute(attn_kernel, cudaFuncAttributeMaxDynamicSharedMemorySize,
                         ATTN_SMEM);

    // 0) convert inputs to fp16 (RN)
    f2h<<<ELEMS / 2 / 256, 256>>>((const float2*)x, (__half2*)xh, ELEMS / 2);
    f2h<<<3 * DM * DM / 2 / 256, 256>>>((const float2*)w_attn, (__half2*)wah,
                                        3 * DM * DM / 2);
    f2h<<<DM * DM / 2 / 256, 256>>>((const float2*)w_proj, (__half2*)wph,
                                    DM * DM / 2);

    // 1) QKV projection -> q/k [B,H,T,dk] (Q pre-scaled), v [B,H,dk,T]
    gemm_h<1><<<dim3(3 * DM / 128, MTOT / 128), 128, GEMM_SMEM>>>(
        xh, wah, b_attn, nullptr, qp, kp, vp, MTOT, 3 * DM, DM);

    // 2) Flash attention -> y fp16 [B,T,C]
    attn_kernel<<<dim3(TS / 128, NH, BB), 256, ATTN_SMEM>>>(qp, kp, vp, yp);

    // 3) Output projection -> d_out (fp32 + bias)
    gemm_h<0><<<dim3(DM / 128, MTOT / 128), 128, GEMM_SMEM>>>(
        yp, wph, b_proj, out, nullptr, nullptr, nullptr, MTOT, DM, DM);
}